// round 1
// baseline (speedup 1.0000x reference)
#include <cuda_runtime.h>
#include <cuda_bf16.h>
#include <math.h>

#define NN 50000
#define NE 600000
#define FDIM 128

// ---------------- scratch (static device globals; no allocation) ----------------
__device__ int   g_deg[NN];
__device__ float g_dinv[NN];
__device__ int   g_rowptr[NN + 1];
__device__ int   g_cursor[NN];
__device__ int   g_col[NE];
__device__ float g_h1[(size_t)NN * FDIM];   // x @ W1
__device__ float g_h [(size_t)NN * FDIM];   // relu(agg1 + b1)
__device__ float g_t [(size_t)NN * 2];      // h @ W2

// ---------------- degree count ----------------
__global__ void zero_deg_kernel() {
    int i = blockIdx.x * blockDim.x + threadIdx.x;
    if (i < NN) g_deg[i] = 0;
}

__global__ void count_deg_kernel(const int* __restrict__ dst) {
    int e = blockIdx.x * blockDim.x + threadIdx.x;
    if (e < NE) atomicAdd(&g_deg[dst[e]], 1);
}

// ---------------- single-block prefix scan over degrees ----------------
// rowptr = exclusive scan of deg (edges only); dinv = rsqrt(deg+1) (self loop);
// cursor initialized to rowptr[i].
__global__ void scan_deg_kernel() {
    __shared__ int ws[32];
    __shared__ int s_carry;
    const int tid  = threadIdx.x;
    const int lane = tid & 31;
    const int warp = tid >> 5;
    if (tid == 0) { s_carry = 0; g_rowptr[0] = 0; }
    __syncthreads();

    for (int base = 0; base < NN; base += 1024) {
        int i = base + tid;
        int v = (i < NN) ? g_deg[i] : 0;
        if (i < NN) g_dinv[i] = rsqrtf((float)(v + 1));

        // warp inclusive scan
        int sc = v;
        #pragma unroll
        for (int off = 1; off < 32; off <<= 1) {
            int n = __shfl_up_sync(0xffffffff, sc, off);
            if (lane >= off) sc += n;
        }
        if (lane == 31) ws[warp] = sc;
        __syncthreads();
        if (warp == 0) {
            int wv = ws[lane];
            int wsc = wv;
            #pragma unroll
            for (int off = 1; off < 32; off <<= 1) {
                int n = __shfl_up_sync(0xffffffff, wsc, off);
                if (lane >= off) wsc += n;
            }
            ws[lane] = wsc - wv; // exclusive warp offsets
        }
        __syncthreads();
        int inc = sc + ws[warp] + s_carry; // inclusive within full array
        if (i < NN) {
            g_rowptr[i + 1] = inc;
            g_cursor[i]     = inc - v; // exclusive
        }
        __syncthreads();
        if (tid == 1023) s_carry = inc;
        __syncthreads();
    }
}

// ---------------- CSR fill (counting sort by dst) ----------------
__global__ void fill_csr_kernel(const int* __restrict__ src, const int* __restrict__ dst) {
    int e = blockIdx.x * blockDim.x + threadIdx.x;
    if (e < NE) {
        int d = dst[e];
        int p = atomicAdd(&g_cursor[d], 1);
        g_col[p] = src[e];
    }
}

// ---------------- GEMM1: h1[M,128] = x[M,128] @ W1[128,128] ----------------
// 128x128 block tile, BK=16, 256 threads, 8x8 register tile per thread.
__global__ void gemm1_kernel(const float* __restrict__ A, const float* __restrict__ W) {
    __shared__ float As[16][128];
    __shared__ float Bs[16][128];
    const int block_row = blockIdx.x * 128;
    const int tid  = threadIdx.x;      // 0..255
    const int tcol = tid & 15;         // 16 col groups
    const int trow = tid >> 4;         // 16 row groups

    float acc[8][8];
    #pragma unroll
    for (int i = 0; i < 8; i++)
        #pragma unroll
        for (int j = 0; j < 8; j++) acc[i][j] = 0.f;

    for (int k0 = 0; k0 < 128; k0 += 16) {
        // A tile: [128 rows][16 k] -> As[k][row]
        #pragma unroll
        for (int l = 0; l < 2; l++) {
            int f  = tid * 2 + l;        // 0..511 float4 slots
            int r  = f >> 2;             // 0..127
            int kq = (f & 3) * 4;        // 0,4,8,12
            int grow = block_row + r;
            float4 v = (grow < NN) ? *(const float4*)&A[(size_t)grow * 128 + k0 + kq]
                                   : make_float4(0.f, 0.f, 0.f, 0.f);
            As[kq + 0][r] = v.x; As[kq + 1][r] = v.y;
            As[kq + 2][r] = v.z; As[kq + 3][r] = v.w;
        }
        // B tile: rows k0..k0+15, all 128 cols
        #pragma unroll
        for (int l = 0; l < 2; l++) {
            int f  = tid * 2 + l;        // 0..511
            int r  = f >> 5;             // 0..15
            int cq = (f & 31) * 4;       // 0..124
            *(float4*)&Bs[r][cq] = *(const float4*)&W[(size_t)(k0 + r) * 128 + cq];
        }
        __syncthreads();
        #pragma unroll
        for (int kk = 0; kk < 16; kk++) {
            float a[8], b[8];
            #pragma unroll
            for (int i = 0; i < 8; i += 4) *(float4*)&a[i] = *(float4*)&As[kk][trow * 8 + i];
            #pragma unroll
            for (int j = 0; j < 8; j += 4) *(float4*)&b[j] = *(float4*)&Bs[kk][tcol * 8 + j];
            #pragma unroll
            for (int i = 0; i < 8; i++)
                #pragma unroll
                for (int j = 0; j < 8; j++) acc[i][j] += a[i] * b[j];
        }
        __syncthreads();
    }
    #pragma unroll
    for (int i = 0; i < 8; i++) {
        int grow = block_row + trow * 8 + i;
        if (grow < NN) {
            #pragma unroll
            for (int j = 0; j < 8; j += 4) {
                *(float4*)&g_h1[(size_t)grow * 128 + tcol * 8 + j] =
                    make_float4(acc[i][j], acc[i][j+1], acc[i][j+2], acc[i][j+3]);
            }
        }
    }
}

// ---------------- Layer-1 aggregation: warp per node, gather-only ----------------
__global__ void agg1_kernel(const float* __restrict__ b1) {
    int node = blockIdx.x * (blockDim.x >> 5) + (threadIdx.x >> 5);
    if (node >= NN) return;
    int lane = threadIdx.x & 31;

    float di = g_dinv[node];
    float4 v = *(const float4*)&g_h1[(size_t)node * 128 + lane * 4];
    float w0 = di * di; // self-loop weight
    float4 acc = make_float4(v.x * w0, v.y * w0, v.z * w0, v.w * w0);

    int beg = g_rowptr[node], end = g_rowptr[node + 1];
    for (int j = beg; j < end; j++) {
        int s = g_col[j];
        float w = g_dinv[s] * di;
        float4 u = *(const float4*)&g_h1[(size_t)s * 128 + lane * 4];
        acc.x += w * u.x; acc.y += w * u.y;
        acc.z += w * u.z; acc.w += w * u.w;
    }
    float4 bb = *(const float4*)&b1[lane * 4];
    acc.x = fmaxf(acc.x + bb.x, 0.f);
    acc.y = fmaxf(acc.y + bb.y, 0.f);
    acc.z = fmaxf(acc.z + bb.z, 0.f);
    acc.w = fmaxf(acc.w + bb.w, 0.f);
    *(float4*)&g_h[(size_t)node * 128 + lane * 4] = acc;
}

// ---------------- Layer-2 transform: t[N,2] = h @ W2[128,2]; warp per node ----------------
__global__ void layer2_transform_kernel(const float* __restrict__ W2) {
    int node = blockIdx.x * (blockDim.x >> 5) + (threadIdx.x >> 5);
    if (node >= NN) return;
    int lane = threadIdx.x & 31;

    float4 hv = *(const float4*)&g_h[(size_t)node * 128 + lane * 4];
    // W2 row-major [128][2]
    const float* w = &W2[(size_t)(lane * 4) * 2];
    float t0 = hv.x * w[0] + hv.y * w[2] + hv.z * w[4] + hv.w * w[6];
    float t1 = hv.x * w[1] + hv.y * w[3] + hv.z * w[5] + hv.w * w[7];
    #pragma unroll
    for (int off = 16; off > 0; off >>= 1) {
        t0 += __shfl_down_sync(0xffffffff, t0, off);
        t1 += __shfl_down_sync(0xffffffff, t1, off);
    }
    if (lane == 0) {
        g_t[(size_t)node * 2 + 0] = t0;
        g_t[(size_t)node * 2 + 1] = t1;
    }
}

// ---------------- Layer-2 aggregation: thread per node (2 features) ----------------
__global__ void agg2_kernel(const float* __restrict__ b2, float* __restrict__ out) {
    int i = blockIdx.x * blockDim.x + threadIdx.x;
    if (i >= NN) return;
    float di = g_dinv[i];
    float w0 = di * di;
    float a0 = w0 * g_t[(size_t)i * 2 + 0];
    float a1 = w0 * g_t[(size_t)i * 2 + 1];
    int beg = g_rowptr[i], end = g_rowptr[i + 1];
    for (int j = beg; j < end; j++) {
        int s = g_col[j];
        float w = g_dinv[s] * di;
        a0 += w * g_t[(size_t)s * 2 + 0];
        a1 += w * g_t[(size_t)s * 2 + 1];
    }
    out[(size_t)i * 2 + 0] = a0 + b2[0];
    out[(size_t)i * 2 + 1] = a1 + b2[1];
}

// ---------------- launch ----------------
extern "C" void kernel_launch(void* const* d_in, const int* in_sizes, int n_in,
                              void* d_out, int out_size) {
    const float* x  = (const float*)d_in[0];
    const int*   ei = (const int*)  d_in[1];   // [2, NE]
    const float* W1 = (const float*)d_in[2];
    const float* b1 = (const float*)d_in[3];
    const float* W2 = (const float*)d_in[4];
    const float* b2 = (const float*)d_in[5];
    float* out = (float*)d_out;

    const int* src = ei;
    const int* dst = ei + NE;

    zero_deg_kernel<<<(NN + 255) / 256, 256>>>();
    count_deg_kernel<<<(NE + 255) / 256, 256>>>(dst);
    scan_deg_kernel<<<1, 1024>>>();
    fill_csr_kernel<<<(NE + 255) / 256, 256>>>(src, dst);

    gemm1_kernel<<<(NN + 127) / 128, 256>>>(x, W1);

    // warp per node, 8 warps per 256-thread block
    agg1_kernel<<<(NN + 7) / 8, 256>>>(b1);
    layer2_transform_kernel<<<(NN + 7) / 8, 256>>>(W2);
    agg2_kernel<<<(NN + 255) / 256, 256>>>(b2, out);
}